// round 6
// baseline (speedup 1.0000x reference)
#include <cuda_runtime.h>

#define HID 768
#define NTOK 8
#define FSZ 32
#define BATCH 64
#define CHUNK 256           // h per chunk
#define NCHUNK (HID / CHUNK)
#define TSTRIDE 33          // 32 + 1 pad

// smem layout (floats)
#define OFF_TS    0                         // [8][768]      t tile
#define OFF_ORIC  (OFF_TS + NTOK * HID)     // [256][33]     centered*rstd chunk
#define OFF_CW    (OFF_ORIC + CHUNK * TSTRIDE) // [256][8]   conv_w chunk (transposed)
#define OFF_PART  (OFF_CW + CHUNK * 8)      // [8 warps][32 y][8 n]
#define OFF_MIX   (OFF_PART + 8 * 256)      // [8 n][32 y]
#define OFF_CS    (OFF_MIX + 256)           // [8] cwsum
#define OFF_LW    (OFF_CS + 8)              // [72] lin_w + lin_b
#define SMEM_FLOATS (OFF_LW + 72)

__device__ __forceinline__ void st_cs_v4(float* p, float4 v) {
    asm volatile("st.global.cs.v4.f32 [%0], {%1,%2,%3,%4};"
                 :: "l"(p), "f"(v.x), "f"(v.y), "f"(v.z), "f"(v.w) : "memory");
}

__global__ __launch_bounds__(256) void fused_kernel(
    const float* __restrict__ token,
    const float* __restrict__ ori,
    const float* __restrict__ ln1_w, const float* __restrict__ ln1_b,
    const float* __restrict__ lin_w, const float* __restrict__ lin_b,
    const float* __restrict__ ln2_w, const float* __restrict__ ln2_b,
    const float* __restrict__ lno_w, const float* __restrict__ lno_b,
    const float* __restrict__ conv_w,
    float* __restrict__ out)
{
    extern __shared__ float sm[];
    float* ts    = sm + OFF_TS;
    float* oric  = sm + OFF_ORIC;
    float* cw    = sm + OFF_CW;
    float* part  = sm + OFF_PART;
    float* mixs  = sm + OFF_MIX;
    float* cwsum = sm + OFF_CS;
    float* lw    = sm + OFF_LW;

    const int tid  = threadIdx.x;
    const int lane = tid & 31;
    const int w    = tid >> 5;              // 8 warps
    const int b    = blockIdx.x >> 5;
    const int x    = blockIdx.x & 31;

    const float* obase = ori + ((size_t)(b * 1024 + x * FSZ)) * HID;

    // ---- Phase A: stage token -> ts, lin weights, cwsum ----
    #pragma unroll
    for (int i = tid; i < NTOK * HID; i += 256)
        ts[i] = __ldg(&token[(size_t)b * NTOK * HID + i]);
    if (tid < 64) lw[tid] = lin_w[tid];
    else if (tid < 72) lw[tid] = lin_b[tid - 64];
    {   // warp w sums conv_w row w
        float cs = 0.f;
        for (int h = lane; h < HID; h += 32) cs += __ldg(&conv_w[w * HID + h]);
        #pragma unroll
        for (int o = 16; o; o >>= 1) cs += __shfl_xor_sync(0xffffffffu, cs, o);
        if (lane == 0) cwsum[w] = cs;
    }
    __syncthreads();

    // ---- Phase B: LN1 (warp w -> token row w) ----
    {
        float sum = 0.f, sq = 0.f;
        for (int h = lane; h < HID; h += 32) { float v = ts[w * HID + h]; sum += v; sq += v * v; }
        #pragma unroll
        for (int o = 16; o; o >>= 1) {
            sum += __shfl_xor_sync(0xffffffffu, sum, o);
            sq  += __shfl_xor_sync(0xffffffffu, sq,  o);
        }
        float mu = sum * (1.f / HID);
        float rs = rsqrtf(sq * (1.f / HID) - mu * mu + 1e-5f);
        for (int h = lane; h < HID; h += 32)
            ts[w * HID + h] = (ts[w * HID + h] - mu) * rs * ln1_w[h] + ln1_b[h];
    }
    __syncthreads();

    // ---- Phase C: Linear over token dim (per-column, thread-owned) ----
    for (int h = tid; h < HID; h += 256) {
        float v[NTOK];
        #pragma unroll
        for (int n = 0; n < NTOK; n++) v[n] = ts[n * HID + h];
        #pragma unroll
        for (int m = 0; m < NTOK; m++) {
            float a = lw[64 + m];
            #pragma unroll
            for (int n = 0; n < NTOK; n++) a += lw[m * NTOK + n] * v[n];
            ts[m * HID + h] = a;
        }
    }
    __syncthreads();

    // ---- Phase D: LN2 -> final t in ts ----
    {
        float sum = 0.f, sq = 0.f;
        for (int h = lane; h < HID; h += 32) { float v = ts[w * HID + h]; sum += v; sq += v * v; }
        #pragma unroll
        for (int o = 16; o; o >>= 1) {
            sum += __shfl_xor_sync(0xffffffffu, sum, o);
            sq  += __shfl_xor_sync(0xffffffffu, sq,  o);
        }
        float mu = sum * (1.f / HID);
        float rs = rsqrtf(sq * (1.f / HID) - mu * mu + 1e-5f);
        for (int h = lane; h < HID; h += 32)
            ts[w * HID + h] = (ts[w * HID + h] - mu) * rs * ln2_w[h] + ln2_b[h];
    }
    // ts is next read only in Phase G; Phase E's syncthreads cover the hazard

    // ---- Phase E: chunked LN-over-y + GEMM  P[n][y] = sum_h cw[n,h]*oric[h,y] ----
    float acc[8];
    #pragma unroll
    for (int n = 0; n < 8; n++) acc[n] = 0.f;

    #pragma unroll
    for (int c = 0; c < NCHUNK; c++) {
        const int h = c * CHUNK + tid;

        // load own h-column (32 y values), streaming
        float xv[FSZ];
        #pragma unroll
        for (int y = 0; y < FSZ; y++) xv[y] = __ldcs(&obase[(size_t)y * HID + h]);

        // conv_w chunk (coalesced per k)
        float cv[8];
        #pragma unroll
        for (int k = 0; k < 8; k++) cv[k] = __ldg(&conv_w[k * HID + h]);

        // per-h LayerNorm over y (biased var, eps = featmap_size = 32.0f)
        float sum = 0.f, sq = 0.f;
        #pragma unroll
        for (int y = 0; y < FSZ; y++) { sum += xv[y]; sq += xv[y] * xv[y]; }
        float mu = sum * (1.f / FSZ);
        float rs = rsqrtf(sq * (1.f / FSZ) - mu * mu + (float)FSZ);

        __syncthreads();   // prior chunk's GEMM reads done before overwrite
        #pragma unroll
        for (int y = 0; y < FSZ; y++)
            oric[tid * TSTRIDE + y] = (xv[y] - mu) * rs;
        *(float4*)&cw[tid * 8]     = make_float4(cv[0], cv[1], cv[2], cv[3]);
        *(float4*)&cw[tid * 8 + 4] = make_float4(cv[4], cv[5], cv[6], cv[7]);
        __syncthreads();

        // warp w covers h-range [w*32, w*32+32) of this chunk; lane = y
        const int hb = w * 32;
        #pragma unroll
        for (int i = 0; i < 32; i++) {
            float o = oric[(hb + i) * TSTRIDE + lane];
            float4 c0 = *(const float4*)&cw[(hb + i) * 8];
            float4 c1 = *(const float4*)&cw[(hb + i) * 8 + 4];
            acc[0] += c0.x * o; acc[1] += c0.y * o; acc[2] += c0.z * o; acc[3] += c0.w * o;
            acc[4] += c1.x * o; acc[5] += c1.y * o; acc[6] += c1.z * o; acc[7] += c1.w * o;
        }
    }

    // write partials: part[w][y][n]
    *(float4*)&part[w * 256 + lane * 8]     = make_float4(acc[0], acc[1], acc[2], acc[3]);
    *(float4*)&part[w * 256 + lane * 8 + 4] = make_float4(acc[4], acc[5], acc[6], acc[7]);
    __syncthreads();

    // ---- Phase F: reduce over warps + sigmoid gate ----
    {
        int n = tid & 7, y = tid >> 3;
        float P = 0.f;
        #pragma unroll
        for (int ww = 0; ww < 8; ww++) P += part[ww * 256 + y * 8 + n];
        float v = lno_w[y] * P + lno_b[y] * cwsum[n];
        mixs[n * 32 + y] = 1.f / (1.f + __expf(-v));
    }
    __syncthreads();

    // ---- Phase G: out[y][h] = sum_n t[n][h] * mix[n][y], float4 streaming stores ----
    float* ob = out + ((size_t)(b * 1024 + x * FSZ)) * HID;
    #pragma unroll
    for (int k = 0; k < 24; k++) {
        int task = tid + k * 256;          // 0..6143 = 32 y * 192 float4
        int y  = task / 192;
        int h4 = (task - y * 192) * 4;
        float4 r = make_float4(0.f, 0.f, 0.f, 0.f);
        #pragma unroll
        for (int n = 0; n < 8; n++) {
            float4 t4 = *(const float4*)&ts[n * HID + h4];
            float  mn = mixs[n * 32 + y];
            r.x += t4.x * mn; r.y += t4.y * mn; r.z += t4.z * mn; r.w += t4.w * mn;
        }
        st_cs_v4(&ob[(size_t)y * HID + h4], r);
    }
}

extern "C" void kernel_launch(void* const* d_in, const int* in_sizes, int n_in,
                              void* d_out, int out_size)
{
    const float* token = (const float*)d_in[0];
    const float* ori   = (const float*)d_in[1];
    const float* ln1_w = (const float*)d_in[2];
    const float* ln1_b = (const float*)d_in[3];
    const float* lin_w = (const float*)d_in[4];
    const float* lin_b = (const float*)d_in[5];
    const float* ln2_w = (const float*)d_in[6];
    const float* ln2_b = (const float*)d_in[7];
    const float* lno_w = (const float*)d_in[8];
    const float* lno_b = (const float*)d_in[9];
    const float* conv_w= (const float*)d_in[10];

    const int smem_bytes = SMEM_FLOATS * sizeof(float);
    cudaFuncSetAttribute(fused_kernel, cudaFuncAttributeMaxDynamicSharedMemorySize, smem_bytes);

    fused_kernel<<<BATCH * FSZ, 256, smem_bytes>>>(
        token, ori, ln1_w, ln1_b, lin_w, lin_b, ln2_w, ln2_b,
        lno_w, lno_b, conv_w, (float*)d_out);
}

// round 8
// speedup vs baseline: 1.3886x; 1.3886x over previous
#include <cuda_runtime.h>

#define HID 768
#define NTOK 8
#define FSZ 32
#define BATCH 64
#define TSTRIDE 33   // 32 + 1 pad: conflict-free [h][y] tile

// scratch (allocation-free rule: device globals)
__device__ float g_t[BATCH * NTOK * HID];
__device__ float g_cwsum[NTOK];

__device__ __forceinline__ void st_cs_v4(float* p, float4 v) {
    asm volatile("st.global.cs.v4.f32 [%0], {%1,%2,%3,%4};"
                 :: "l"(p), "f"(v.x), "f"(v.y), "f"(v.z), "f"(v.w) : "memory");
}

// ---------------------------------------------------------------------------
// Kernel 1: t = LN2( Linear_over_tokens( LN1(token) ) )  + cwsum side output
// grid = BATCH+1 blocks, 256 threads
// ---------------------------------------------------------------------------
__global__ __launch_bounds__(256) void prep_kernel(
    const float* __restrict__ token,
    const float* __restrict__ ln1_w, const float* __restrict__ ln1_b,
    const float* __restrict__ lin_w, const float* __restrict__ lin_b,
    const float* __restrict__ ln2_w, const float* __restrict__ ln2_b,
    const float* __restrict__ conv_w)
{
    __shared__ float s[NTOK][HID];
    __shared__ float lw[NTOK * NTOK + NTOK];

    int b    = blockIdx.x;
    int tid  = threadIdx.x;
    int lane = tid & 31;
    int w    = tid >> 5;      // 8 warps

    if (b == BATCH) {
        float sum = 0.f;
        for (int h = lane; h < HID; h += 32) sum += conv_w[w * HID + h];
        #pragma unroll
        for (int o = 16; o; o >>= 1) sum += __shfl_xor_sync(0xffffffffu, sum, o);
        if (lane == 0) g_cwsum[w] = sum;
        return;
    }

    if (tid < NTOK * NTOK) lw[tid] = lin_w[tid];
    if (tid < NTOK)        lw[NTOK * NTOK + tid] = lin_b[tid];

    for (int i = tid; i < NTOK * HID; i += 256)
        s[0][i] = token[(size_t)b * NTOK * HID + i];
    __syncthreads();

    // LN1: warp w -> token row w
    {
        float sum = 0.f, sq = 0.f;
        for (int h = lane; h < HID; h += 32) { float v = s[w][h]; sum += v; sq += v * v; }
        #pragma unroll
        for (int o = 16; o; o >>= 1) {
            sum += __shfl_xor_sync(0xffffffffu, sum, o);
            sq  += __shfl_xor_sync(0xffffffffu, sq,  o);
        }
        float mu = sum * (1.f / HID);
        float rs = rsqrtf(sq * (1.f / HID) - mu * mu + 1e-5f);
        for (int h = lane; h < HID; h += 32)
            s[w][h] = (s[w][h] - mu) * rs * ln1_w[h] + ln1_b[h];
    }
    __syncthreads();

    // Linear over token dim
    for (int h = tid; h < HID; h += 256) {
        float v[NTOK];
        #pragma unroll
        for (int n = 0; n < NTOK; n++) v[n] = s[n][h];
        #pragma unroll
        for (int m = 0; m < NTOK; m++) {
            float a = lw[NTOK * NTOK + m];
            #pragma unroll
            for (int n = 0; n < NTOK; n++) a += lw[m * NTOK + n] * v[n];
            s[m][h] = a;
        }
    }
    __syncthreads();

    // LN2 + store g_t
    {
        float sum = 0.f, sq = 0.f;
        for (int h = lane; h < HID; h += 32) { float v = s[w][h]; sum += v; sq += v * v; }
        #pragma unroll
        for (int o = 16; o; o >>= 1) {
            sum += __shfl_xor_sync(0xffffffffu, sum, o);
            sq  += __shfl_xor_sync(0xffffffffu, sq,  o);
        }
        float mu = sum * (1.f / HID);
        float rs = rsqrtf(sq * (1.f / HID) - mu * mu + 1e-5f);
        for (int h = lane; h < HID; h += 32)
            g_t[((size_t)b * NTOK + w) * HID + h] = (s[w][h] - mu) * rs * ln2_w[h] + ln2_b[h];
    }
}

// ---------------------------------------------------------------------------
// Kernel 2: per (b,x) tile of 32 y-rows. 768 threads, 24 warps, 1 block/SM.
//   Phase L: thread tid owns h-column tid; LN over y in regs -> oric smem
//   Phase M: warp w: P_partial[n][y] over h in [w*32, w*32+32)
//   Phase F: reduce + sigmoid -> mixs
//   Phase G: t held in REGISTERS (key change): thread (g=tid/192, j=tid%192)
//            owns h-quad 4j and y in [8g, 8g+8); 8 LDG.128 of g_t,
//            64 broadcast LDS of mix, 8 STG.128. No ts smem at all.
// ---------------------------------------------------------------------------
#define NWARP 24
#define SMEM_FLOATS (HID * TSTRIDE + HID * 8 + NWARP * 256 + 256)

__global__ __launch_bounds__(768, 1) void main_kernel(
    const float* __restrict__ ori,
    const float* __restrict__ lno_w, const float* __restrict__ lno_b,
    const float* __restrict__ conv_w,
    float* __restrict__ out)
{
    extern __shared__ float sm[];
    float* oric = sm;                        // [768][33] centered*rstd tile
    float* cw   = oric + HID * TSTRIDE;      // [768][8]  conv_w transposed
    float* part = cw + HID * 8;              // [24][32 y][8 n]
    float* mixs = part + NWARP * 256;        // [8 n][32 y]

    const int tid  = threadIdx.x;
    const int lane = tid & 31;
    const int w    = tid >> 5;
    const int b    = blockIdx.x >> 5;
    const int x    = blockIdx.x & 31;

    const float* obase = ori + ((size_t)(b * 1024 + x * FSZ)) * HID;

    // ---- Phase L: load own h-column (streaming), stage cw ----
    float xv[FSZ];
    #pragma unroll
    for (int y = 0; y < FSZ; y++) xv[y] = __ldcs(&obase[(size_t)y * HID + tid]);
    #pragma unroll
    for (int k = 0; k < NTOK; k++)
        cw[tid * 8 + k] = __ldg(&conv_w[k * HID + tid]);

    // per-h LayerNorm over y (biased var, eps = featmap_size = 32.0f)
    {
        float sum = 0.f, sq = 0.f;
        #pragma unroll
        for (int y = 0; y < FSZ; y++) { sum += xv[y]; sq += xv[y] * xv[y]; }
        float mu = sum * (1.f / FSZ);
        float rs = rsqrtf(sq * (1.f / FSZ) - mu * mu + (float)FSZ);
        #pragma unroll
        for (int y = 0; y < FSZ; y++)
            oric[tid * TSTRIDE + y] = (xv[y] - mu) * rs;
    }
    __syncthreads();

    // ---- Phase M: warp w covers h in [w*32, w*32+32), lane = y ----
    {
        float acc[8];
        #pragma unroll
        for (int n = 0; n < 8; n++) acc[n] = 0.f;
        const int hb = w * 32;
        #pragma unroll
        for (int i = 0; i < 32; i++) {
            float o = oric[(hb + i) * TSTRIDE + lane];
            float4 c0 = *(const float4*)&cw[(hb + i) * 8];
            float4 c1 = *(const float4*)&cw[(hb + i) * 8 + 4];
            acc[0] += c0.x * o; acc[1] += c0.y * o; acc[2] += c0.z * o; acc[3] += c0.w * o;
            acc[4] += c1.x * o; acc[5] += c1.y * o; acc[6] += c1.z * o; acc[7] += c1.w * o;
        }
        *(float4*)&part[w * 256 + lane * 8]     = make_float4(acc[0], acc[1], acc[2], acc[3]);
        *(float4*)&part[w * 256 + lane * 8 + 4] = make_float4(acc[4], acc[5], acc[6], acc[7]);
    }

    // Load t into registers while GEMM partials settle (overlaps LDG latency).
    const int g  = tid / 192;            // y-group 0..3 (uniform per warp)
    const int j  = tid - g * 192;        // float4 index within h row
    float4 tv[NTOK];
    #pragma unroll
    for (int n = 0; n < NTOK; n++)
        tv[n] = *(const float4*)&g_t[((size_t)b * NTOK + n) * HID + 4 * j];

    __syncthreads();

    // ---- Phase F: reduce partials + sigmoid gate ----
    if (tid < 256) {
        int n = tid & 7, y = tid >> 3;
        float P = 0.f;
        #pragma unroll
        for (int ww = 0; ww < NWARP; ww++) P += part[ww * 256 + y * 8 + n];
        float v = lno_w[y] * P + lno_b[y] * g_cwsum[n];
        mixs[n * 32 + y] = 1.f / (1.f + __expf(-v));
    }
    __syncthreads();

    // ---- Phase G: out[y][4j..4j+4) = sum_n tv[n] * mix[n][y], y in [8g, 8g+8) ----
    float* ob = out + ((size_t)(b * 1024 + x * FSZ)) * HID;
    #pragma unroll
    for (int yy = 0; yy < 8; yy++) {
        const int y = g * 8 + yy;
        float4 r = make_float4(0.f, 0.f, 0.f, 0.f);
        #pragma unroll
        for (int n = 0; n < 8; n++) {
            float mn = mixs[n * 32 + y];   // uniform per warp -> broadcast LDS
            r.x += tv[n].x * mn; r.y += tv[n].y * mn;
            r.z += tv[n].z * mn; r.w += tv[n].w * mn;
        }
        st_cs_v4(&ob[(size_t)y * HID + 4 * j], r);
    }
}

// ---------------------------------------------------------------------------
extern "C" void kernel_launch(void* const* d_in, const int* in_sizes, int n_in,
                              void* d_out, int out_size)
{
    const float* token = (const float*)d_in[0];
    const float* ori   = (const float*)d_in[1];
    const float* ln1_w = (const float*)d_in[2];
    const float* ln1_b = (const float*)d_in[3];
    const float* lin_w = (const float*)d_in[4];
    const float* lin_b = (const float*)d_in[5];
    const float* ln2_w = (const float*)d_in[6];
    const float* ln2_b = (const float*)d_in[7];
    const float* lno_w = (const float*)d_in[8];
    const float* lno_b = (const float*)d_in[9];
    const float* conv_w= (const float*)d_in[10];

    const int smem_bytes = SMEM_FLOATS * sizeof(float);
    cudaFuncSetAttribute(main_kernel, cudaFuncAttributeMaxDynamicSharedMemorySize, smem_bytes);

    prep_kernel<<<BATCH + 1, 256>>>(token, ln1_w, ln1_b, lin_w, lin_b,
                                    ln2_w, ln2_b, conv_w);
    main_kernel<<<BATCH * FSZ, 768, smem_bytes>>>(ori, lno_w, lno_b, conv_w,
                                                  (float*)d_out);
}

// round 11
// speedup vs baseline: 1.8034x; 1.2987x over previous
#include <cuda_runtime.h>

#define HID 768
#define NTOK 8
#define FSZ 32
#define BATCH 64

__device__ float g_t[BATCH * NTOK * HID];
__device__ float g_cwsum[NTOK];

__device__ __forceinline__ void st_cs_v4(float* p, float4 v) {
    asm volatile("st.global.cs.v4.f32 [%0], {%1,%2,%3,%4};"
                 :: "l"(p), "f"(v.x), "f"(v.y), "f"(v.z), "f"(v.w) : "memory");
}
__device__ __forceinline__ float4 ld_cs_v4(const float* p) {
    float4 v;
    asm volatile("ld.global.cs.v4.f32 {%0,%1,%2,%3}, [%4];"
                 : "=f"(v.x), "=f"(v.y), "=f"(v.z), "=f"(v.w) : "l"(p));
    return v;
}

// ---------------------------------------------------------------------------
// Kernel 1: t = LN2( Linear_over_tokens( LN1(token) ) ) + cwsum  (unchanged)
// ---------------------------------------------------------------------------
__global__ __launch_bounds__(256) void prep_kernel(
    const float* __restrict__ token,
    const float* __restrict__ ln1_w, const float* __restrict__ ln1_b,
    const float* __restrict__ lin_w, const float* __restrict__ lin_b,
    const float* __restrict__ ln2_w, const float* __restrict__ ln2_b,
    const float* __restrict__ conv_w)
{
    __shared__ float s[NTOK][HID];
    __shared__ float lw[NTOK * NTOK + NTOK];

    int b = blockIdx.x, tid = threadIdx.x, lane = tid & 31, w = tid >> 5;

    if (b == BATCH) {
        float sum = 0.f;
        for (int h = lane; h < HID; h += 32) sum += conv_w[w * HID + h];
        #pragma unroll
        for (int o = 16; o; o >>= 1) sum += __shfl_xor_sync(0xffffffffu, sum, o);
        if (lane == 0) g_cwsum[w] = sum;
        return;
    }

    if (tid < NTOK * NTOK) lw[tid] = lin_w[tid];
    if (tid < NTOK)        lw[NTOK * NTOK + tid] = lin_b[tid];
    for (int i = tid; i < NTOK * HID; i += 256)
        s[0][i] = token[(size_t)b * NTOK * HID + i];
    __syncthreads();

    {   // LN1
        float sum = 0.f, sq = 0.f;
        for (int h = lane; h < HID; h += 32) { float v = s[w][h]; sum += v; sq += v * v; }
        #pragma unroll
        for (int o = 16; o; o >>= 1) {
            sum += __shfl_xor_sync(0xffffffffu, sum, o);
            sq  += __shfl_xor_sync(0xffffffffu, sq,  o);
        }
        float mu = sum * (1.f / HID);
        float rs = rsqrtf(sq * (1.f / HID) - mu * mu + 1e-5f);
        for (int h = lane; h < HID; h += 32)
            s[w][h] = (s[w][h] - mu) * rs * ln1_w[h] + ln1_b[h];
    }
    __syncthreads();

    for (int h = tid; h < HID; h += 256) {   // Linear over tokens
        float v[NTOK];
        #pragma unroll
        for (int n = 0; n < NTOK; n++) v[n] = s[n][h];
        #pragma unroll
        for (int m = 0; m < NTOK; m++) {
            float a = lw[NTOK * NTOK + m];
            #pragma unroll
            for (int n = 0; n < NTOK; n++) a += lw[m * NTOK + n] * v[n];
            s[m][h] = a;
        }
    }
    __syncthreads();

    {   // LN2 -> g_t
        float sum = 0.f, sq = 0.f;
        for (int h = lane; h < HID; h += 32) { float v = s[w][h]; sum += v; sq += v * v; }
        #pragma unroll
        for (int o = 16; o; o >>= 1) {
            sum += __shfl_xor_sync(0xffffffffu, sum, o);
            sq  += __shfl_xor_sync(0xffffffffu, sq,  o);
        }
        float mu = sum * (1.f / HID);
        float rs = rsqrtf(sq * (1.f / HID) - mu * mu + 1e-5f);
        for (int h = lane; h < HID; h += 32)
            g_t[((size_t)b * NTOK + w) * HID + h] = (s[w][h] - mu) * rs * ln2_w[h] + ln2_b[h];
    }
}

// ---------------------------------------------------------------------------
// Kernel 2: 256 threads, 3 blocks/SM, ~60 KB smem. Per (b,x) tile:
//  S: coalesced read (DRAM) -> per-h mu,rs (no value storage);
//     w'[n,h]=cw*rs smem, c0[n]=sum cw*mu*rs
//  G: GEMM re-reads ori ROW-MAJOR from L2:  P[n,y] = sum_h w'[n,h]*ori[y,h] - c0[n]
//     partials: part[r=y*8+n][lane], scalar STS (warp-uniform r -> conflict-free)
//  F: thread tid reduces row tid over 32 lanes + sigmoid -> mixs
//  O: t in registers, out[y][h] = sum_n t*mix, streaming stores
// ---------------------------------------------------------------------------
#define PSTRIDE 33
#define OFF_WP   0                            // [8][768]
#define OFF_PART (OFF_WP + 8 * HID)           // [256][33] (rows r=y*8+n; also c0 staging [48])
#define OFF_MIX  (OFF_PART + 256 * PSTRIDE)   // [8][32]
#define OFF_C0   (OFF_MIX + 256)              // [8]
#define OFF_CWS  (OFF_C0 + 8)                 // [8]
#define OFF_LNW  (OFF_CWS + 8)                // [32]
#define OFF_LNB  (OFF_LNW + 32)               // [32]
#define SMEM_FLOATS (OFF_LNB + 32)

__global__ __launch_bounds__(256, 3) void main_kernel(
    const float* __restrict__ ori,
    const float* __restrict__ lno_w, const float* __restrict__ lno_b,
    const float* __restrict__ conv_w,
    float* __restrict__ out)
{
    extern __shared__ float sm[];
    float* wp   = sm + OFF_WP;
    float* part = sm + OFF_PART;
    float* mixs = sm + OFF_MIX;
    float* c0s  = sm + OFF_C0;
    float* cws  = sm + OFF_CWS;
    float* lnw  = sm + OFF_LNW;
    float* lnb  = sm + OFF_LNB;

    const int tid  = threadIdx.x;
    const int lane = tid & 31;
    const int w    = tid >> 5;
    const int b    = blockIdx.x >> 5;
    const int x    = blockIdx.x & 31;

    const float* obase = ori + ((size_t)(b * 1024 + x * FSZ)) * HID;

    if (tid < 32) { lnw[tid] = lno_w[tid]; lnb[tid] = lno_b[tid]; }
    if (tid < 8)  cws[tid] = g_cwsum[tid];

    // ---- Phase S: stats + w' (threads < 192, float4 column j = tid) ----
    float c0p[8];
    #pragma unroll
    for (int n = 0; n < 8; n++) c0p[n] = 0.f;

    if (tid < 192) {
        float4 s4 = make_float4(0.f, 0.f, 0.f, 0.f);
        float4 q4 = make_float4(0.f, 0.f, 0.f, 0.f);
        #pragma unroll
        for (int y = 0; y < FSZ; y++) {
            float4 o4 = *(const float4*)&obase[(size_t)y * HID + 4 * tid];
            s4.x += o4.x; s4.y += o4.y; s4.z += o4.z; s4.w += o4.w;
            q4.x += o4.x * o4.x; q4.y += o4.y * o4.y;
            q4.z += o4.z * o4.z; q4.w += o4.w * o4.w;
        }
        const float inv = 1.f / FSZ, eps = (float)FSZ;
        float4 mu4 = make_float4(s4.x * inv, s4.y * inv, s4.z * inv, s4.w * inv);
        float4 rs4;
        rs4.x = rsqrtf(q4.x * inv - mu4.x * mu4.x + eps);
        rs4.y = rsqrtf(q4.y * inv - mu4.y * mu4.y + eps);
        rs4.z = rsqrtf(q4.z * inv - mu4.z * mu4.z + eps);
        rs4.w = rsqrtf(q4.w * inv - mu4.w * mu4.w + eps);
        float4 mr4 = make_float4(mu4.x * rs4.x, mu4.y * rs4.y,
                                 mu4.z * rs4.z, mu4.w * rs4.w);
        #pragma unroll
        for (int n = 0; n < 8; n++) {
            float4 c4 = *(const float4*)&conv_w[n * HID + 4 * tid];
            float4 w4 = make_float4(c4.x * rs4.x, c4.y * rs4.y,
                                    c4.z * rs4.z, c4.w * rs4.w);
            *(float4*)&wp[n * HID + 4 * tid] = w4;
            c0p[n] += c4.x * mr4.x + c4.y * mr4.y + c4.z * mr4.z + c4.w * mr4.w;
        }
    }
    // c0 reduce: warps 0..5 butterfly, leader stages into part[0..47]
    if (w < 6) {
        #pragma unroll
        for (int n = 0; n < 8; n++) {
            #pragma unroll
            for (int o = 16; o; o >>= 1)
                c0p[n] += __shfl_xor_sync(0xffffffffu, c0p[n], o);
        }
        if (lane == 0) {
            #pragma unroll
            for (int n = 0; n < 8; n++) part[w * 8 + n] = c0p[n];
        }
    }
    __syncthreads();
    if (tid < 8) {
        float s = 0.f;
        #pragma unroll
        for (int ww = 0; ww < 6; ww++) s += part[ww * 8 + tid];
        c0s[tid] = s;
    }
    // Safe without extra sync: the staging rows (part[0..47]) are only
    // overwritten below by warp 0's own GEMM stores (r<2 rows), and the
    // tid<8 reads above precede those stores in warp-0 program order.
    // c0s is read only after the post-GEMM __syncthreads.

    // ---- Phase G: GEMM, rows y = w + 8*yy, re-read ori from L2 (streaming) ----
    float acc[4][8];
    #pragma unroll
    for (int yy = 0; yy < 4; yy++)
        #pragma unroll
        for (int n = 0; n < 8; n++) acc[yy][n] = 0.f;

    #pragma unroll
    for (int k = 0; k < 6; k++) {
        const int j = lane + 32 * k;
        float4 o4[4];
        #pragma unroll
        for (int yy = 0; yy < 4; yy++)
            o4[yy] = ld_cs_v4(&obase[(size_t)(w + 8 * yy) * HID + 4 * j]);
        #pragma unroll
        for (int n = 0; n < 8; n++) {
            float4 w4 = *(const float4*)&wp[n * HID + 4 * j];
            #pragma unroll
            for (int yy = 0; yy < 4; yy++) {
                acc[yy][n] = fmaf(w4.x, o4[yy].x, acc[yy][n]);
                acc[yy][n] = fmaf(w4.y, o4[yy].y, acc[yy][n]);
                acc[yy][n] = fmaf(w4.z, o4[yy].z, acc[yy][n]);
                acc[yy][n] = fmaf(w4.w, o4[yy].w, acc[yy][n]);
            }
        }
    }
    // scalar partial stores: r = (w+8*yy)*8+n is warp-uniform, lane varies
    // -> consecutive addresses, conflict-free, 4B-aligned (no wide-op trap)
    #pragma unroll
    for (int yy = 0; yy < 4; yy++) {
        const int rbase = (w + 8 * yy) * 8;
        #pragma unroll
        for (int n = 0; n < 8; n++)
            part[(rbase + n) * PSTRIDE + lane] = acc[yy][n];
    }

    // prefetch t into registers (overlaps with sync + reduce)
    float4 tv[NTOK];
    if (tid < 192) {
        #pragma unroll
        for (int n = 0; n < NTOK; n++)
            tv[n] = *(const float4*)&g_t[((size_t)b * NTOK + n) * HID + 4 * tid];
    }
    __syncthreads();

    // ---- Phase F: thread tid reduces row tid (r = y*8+n) + sigmoid ----
    {
        const int n = tid & 7, y = tid >> 3;
        float P = 0.f;
        #pragma unroll
        for (int l = 0; l < 32; l++)
            P += part[tid * PSTRIDE + l];   // banks (tid+l)%32: conflict-free
        P -= c0s[n];
        float v = lnw[y] * P + lnb[y] * cws[n];
        mixs[n * 32 + y] = 1.f / (1.f + __expf(-v));
    }
    __syncthreads();

    // ---- Phase O: out[y][4*tid..+4) = sum_n tv[n]*mix[n][y] ----
    if (tid < 192) {
        float* ob = out + ((size_t)(b * 1024 + x * FSZ)) * HID;
        #pragma unroll
        for (int y = 0; y < FSZ; y++) {
            float4 r = make_float4(0.f, 0.f, 0.f, 0.f);
            #pragma unroll
            for (int n = 0; n < NTOK; n++) {
                float mn = mixs[n * 32 + y];  // warp-uniform -> broadcast LDS
                r.x += tv[n].x * mn; r.y += tv[n].y * mn;
                r.z += tv[n].z * mn; r.w += tv[n].w * mn;
            }
            st_cs_v4(&ob[(size_t)y * HID + 4 * tid], r);
        }
    }
}

// ---------------------------------------------------------------------------
extern "C" void kernel_launch(void* const* d_in, const int* in_sizes, int n_in,
                              void* d_out, int out_size)
{
    const float* token = (const float*)d_in[0];
    const float* ori   = (const float*)d_in[1];
    const float* ln1_w = (const float*)d_in[2];
    const float* ln1_b = (const float*)d_in[3];
    const float* lin_w = (const float*)d_in[4];
    const float* lin_b = (const float*)d_in[5];
    const float* ln2_w = (const float*)d_in[6];
    const float* ln2_b = (const float*)d_in[7];
    const float* lno_w = (const float*)d_in[8];
    const float* lno_b = (const float*)d_in[9];
    const float* conv_w= (const float*)d_in[10];

    const int smem_bytes = SMEM_FLOATS * sizeof(float);
    cudaFuncSetAttribute(main_kernel, cudaFuncAttributeMaxDynamicSharedMemorySize, smem_bytes);

    prep_kernel<<<BATCH + 1, 256>>>(token, ln1_w, ln1_b, lin_w, lin_b,
                                    ln2_w, ln2_b, conv_w);
    main_kernel<<<BATCH * FSZ, 256, smem_bytes>>>(ori, lno_w, lno_b, conv_w,
                                                  (float*)d_out);
}